// round 1
// baseline (speedup 1.0000x reference)
#include <cuda_runtime.h>
#include <cuda_bf16.h>
#include <math.h>

// Problem constants
#define BATCH 64
#define NN    1023        // total nodes
#define PROC  511         // processed (internal) nodes: 0..510
#define HH    512
#define EE    512
#define VOCAB 32
#define OPS   16
#define GG    2048        // packed gates: q = 4*h + j, j in {i,f,g,o}

// ---------------- device scratch (static, allocation-free) ----------------
__device__ float g_h[(size_t)BATCH * PROC * HH];   // h for nodes 0..510
__device__ float g_c[(size_t)BATCH * PROC * HH];   // c for nodes 0..510
__device__ float g_Whp[(size_t)GG * 1024];         // packed W_hh rows (2048 x 1024)
__device__ float g_P[VOCAB * GG];                  // emb_table @ W_ih_needed^T
__device__ float g_biasp[GG];
__device__ float g_wlast[GG];                      // W_ih[r(q), E-1]
__device__ int   g_tnode[PROC * BATCH];            // node type, index node*64+b
__device__ float g_dnode[PROC * BATCH];            // delta for last-emb-element swap

__device__ __forceinline__ float sigmoidf(float x) {
    return 1.0f / (1.0f + expf(-x));
}
__device__ __forceinline__ int packed_row(int q) {
    // q = 4*h + j  ->  original gate row r = j*1024 + h   (keep first H of each 2H gate)
    return (q & 3) * 1024 + (q >> 2);
}

// ---------------- prep kernels ----------------
__global__ void prep_small_kernel(const float* __restrict__ W_ih,
                                  const float* __restrict__ b_ih,
                                  const float* __restrict__ b_hh) {
    int q = blockIdx.x * blockDim.x + threadIdx.x;
    if (q >= GG) return;
    int r = packed_row(q);
    g_biasp[q] = b_ih[r] + b_hh[r];
    g_wlast[q] = W_ih[(size_t)r * EE + (EE - 1)];
}

__global__ void pack_whh_kernel(const float* __restrict__ W_hh) {
    int q = blockIdx.x;                 // 0..2047
    int r = packed_row(q);
    const float4* src = (const float4*)(W_hh + (size_t)r * 1024);
    float4* dst = (float4*)(g_Whp + (size_t)q * 1024);
    dst[threadIdx.x] = src[threadIdx.x];   // 256 threads * float4 = 1024 floats
}

__global__ void compP_kernel(const float* __restrict__ emb_table,
                             const float* __restrict__ W_ih) {
    __shared__ float se[EE];
    int t = blockIdx.x;                 // vocab entry
    for (int i = threadIdx.x; i < EE; i += blockDim.x)
        se[i] = emb_table[(size_t)t * EE + i];
    __syncthreads();
    int q = blockIdx.y * blockDim.x + threadIdx.x;   // 8 * 256 = 2048
    int r = packed_row(q);
    const float4* w = (const float4*)(W_ih + (size_t)r * EE);
    const float4* s4 = (const float4*)se;
    float acc = 0.f;
#pragma unroll 8
    for (int e = 0; e < EE / 4; e++) {
        float4 a = s4[e], b = w[e];
        acc += a.x * b.x + a.y * b.y + a.z * b.z + a.w * b.w;
    }
    g_P[t * GG + q] = acc;
}

__global__ void node_meta_kernel(const int* __restrict__ node_types,
                                 const float* __restrict__ node_args,
                                 const float* __restrict__ emb_table) {
    int i = blockIdx.x * blockDim.x + threadIdx.x;   // node*64 + b
    if (i >= PROC * BATCH) return;
    int node = i >> 6;
    int b = i & 63;
    int t = node_types[(size_t)b * NN + node];
    g_tnode[i] = t;
    float d = 0.f;
    if (t <= 1)   // INT_TYPES_MAX = 1
        d = node_args[(size_t)b * NN + node] - emb_table[(size_t)t * EE + (EE - 1)];
    g_dnode[i] = d;
}

// ---------------- leaf level (d=8): children are all-zero leaves ----------------
// gates = P[t] + delta*wlast + bias; c0 = 0 -> c = sig(i)*tanh(g); h = sig(o)*tanh(c)
__global__ void leaf_level_kernel() {
    int i = blockIdx.x;                 // 0 .. 64*256-1
    int node = 255 + (i >> 6);
    int b = i & 63;
    int ni = node * BATCH + b;
    int t = g_tnode[ni];
    float dd = g_dnode[ni];
    const float4* Pv = (const float4*)(g_P + t * GG);
    const float4* Wl = (const float4*)g_wlast;
    const float4* Bp = (const float4*)g_biasp;
    float* hrow = g_h + ((size_t)b * PROC + node) * HH;
    float* crow = g_c + ((size_t)b * PROC + node) * HH;
#pragma unroll
    for (int j = 0; j < 4; j++) {
        int h = threadIdx.x + 128 * j;  // 128 threads
        float4 pv = Pv[h], wl = Wl[h], bp = Bp[h];
        float gi = pv.x + dd * wl.x + bp.x;
        float gg = pv.z + dd * wl.z + bp.z;
        float go = pv.w + dd * wl.w + bp.w;
        float cn = sigmoidf(gi) * tanhf(gg);
        float hn = sigmoidf(go) * tanhf(cn);
        hrow[h] = hn;
        crow[h] = cn;
    }
}

// ---------------- internal levels (d=7..0): GEMM + fused LSTM epilogue ----------------
// out[m][q] = sum_k h0[m][k] * Whp[q][k],  m = n_local*64 + b, K = 1024
// h0[m][k] = h[b, left][k] (k<512) or h[b, right][k-512]
// 64x64 tile, BK=32, 256 threads, 4x4 micro-tile. Block = (one n_local) x (64 q's = 16 h x 4 gates)
__global__ __launch_bounds__(256) void level_kernel(int first) {
    int node = first + blockIdx.x;
    int left = 2 * node + 1;
    int right = left + 1;
    int q0 = blockIdx.y * 64;

    __shared__ float As[32][64];   // [k][b]
    __shared__ float Bs[32][64];   // [k][q-offset]

    int tid = threadIdx.x;
    int row_t = tid >> 4;          // 0..15
    int col_t = tid & 15;          // 0..15

    // loader mapping: lm = row (b or q-offset), two float4 k-slots per thread
    int lm = tid & 63;
    int lkb = (tid >> 6) * 2;      // kslot base: 0,2,4,6

    float acc[4][4];
#pragma unroll
    for (int i = 0; i < 4; i++)
#pragma unroll
        for (int j = 0; j < 4; j++) acc[i][j] = 0.f;

    for (int k0 = 0; k0 < 1024; k0 += 32) {
        int child = (k0 < 512) ? left : right;
        int kb = k0 & 511;
        const float* arow = g_h + ((size_t)lm * PROC + child) * HH + kb;
        const float* brow = g_Whp + (size_t)(q0 + lm) * 1024 + k0;
#pragma unroll
        for (int s = 0; s < 2; s++) {
            int ks = lkb + s;
            float4 va = *(const float4*)(arow + 4 * ks);
            As[4 * ks + 0][lm] = va.x;
            As[4 * ks + 1][lm] = va.y;
            As[4 * ks + 2][lm] = va.z;
            As[4 * ks + 3][lm] = va.w;
            float4 vb = *(const float4*)(brow + 4 * ks);
            Bs[4 * ks + 0][lm] = vb.x;
            Bs[4 * ks + 1][lm] = vb.y;
            Bs[4 * ks + 2][lm] = vb.z;
            Bs[4 * ks + 3][lm] = vb.w;
        }
        __syncthreads();
#pragma unroll
        for (int kk = 0; kk < 32; kk++) {
            float a[4];
#pragma unroll
            for (int i = 0; i < 4; i++) a[i] = As[kk][row_t + 16 * i];
            float4 bv = *(const float4*)&Bs[kk][4 * col_t];
            float bf[4] = {bv.x, bv.y, bv.z, bv.w};
#pragma unroll
            for (int i = 0; i < 4; i++)
#pragma unroll
                for (int j = 0; j < 4; j++) acc[i][j] += a[i] * bf[j];
        }
        __syncthreads();
    }

    // fused epilogue: cols 4*col_t..+3 are gates {i,f,g,o} of h-index hidx
    int hidx = (q0 >> 2) + col_t;
    int q = q0 + 4 * col_t;
    float4 wl = *(const float4*)&g_wlast[q];
    float4 bp = *(const float4*)&g_biasp[q];
#pragma unroll
    for (int i = 0; i < 4; i++) {
        int b = row_t + 16 * i;
        int ni = node * BATCH + b;
        int t = g_tnode[ni];
        float dd = g_dnode[ni];
        float4 pv = *(const float4*)&g_P[t * GG + q];
        float gi = acc[i][0] + pv.x + dd * wl.x + bp.x;
        float gf = acc[i][1] + pv.y + dd * wl.y + bp.y;
        float gg = acc[i][2] + pv.z + dd * wl.z + bp.z;
        float go = acc[i][3] + pv.w + dd * wl.w + bp.w;
        float c0 = g_c[((size_t)b * PROC + left) * HH + hidx];
        float cn = sigmoidf(gf) * c0 + sigmoidf(gi) * tanhf(gg);
        float hn = sigmoidf(go) * tanhf(cn);
        g_h[((size_t)b * PROC + node) * HH + hidx] = hn;
        g_c[((size_t)b * PROC + node) * HH + hidx] = cn;
    }
}

// ---------------- output head: relu(root_h@W1^T+b1) @ W2^T + b2 + log(valid) -> softmax(/3)
__global__ void head_kernel(const float* __restrict__ W1, const float* __restrict__ b1,
                            const float* __restrict__ W2, const float* __restrict__ b2,
                            const float* __restrict__ validity, float* __restrict__ out) {
    int b = blockIdx.x;
    __shared__ float sh[HH];
    __shared__ float sx[HH];
    __shared__ float slog[OPS];
    const float* rh = g_h + ((size_t)b * PROC + 0) * HH;
    for (int i = threadIdx.x; i < HH; i += blockDim.x) sh[i] = rh[i];
    __syncthreads();
    for (int j = threadIdx.x; j < HH; j += blockDim.x) {
        float acc = b1[j];
        const float4* w = (const float4*)(W1 + (size_t)j * HH);
        const float4* s4 = (const float4*)sh;
#pragma unroll 8
        for (int e = 0; e < HH / 4; e++) {
            float4 a = s4[e], ww = w[e];
            acc += a.x * ww.x + a.y * ww.y + a.z * ww.z + a.w * ww.w;
        }
        sx[j] = fmaxf(acc, 0.f);
    }
    __syncthreads();
    int warp = threadIdx.x >> 5, lane = threadIdx.x & 31;
    for (int o = warp; o < OPS; o += 8) {
        float acc = 0.f;
        const float* w = W2 + (size_t)o * HH;
        for (int e = lane; e < HH; e += 32) acc += sx[e] * w[e];
#pragma unroll
        for (int off = 16; off; off >>= 1) acc += __shfl_xor_sync(0xffffffff, acc, off);
        if (lane == 0) slog[o] = acc + b2[o] + logf(validity[b * OPS + o]);
    }
    __syncthreads();
    if (threadIdx.x == 0) {
        float mx = -1e30f;
        float v[OPS];
        for (int o = 0; o < OPS; o++) { v[o] = slog[o] / 3.0f; if (v[o] > mx) mx = v[o]; }
        float s = 0.f;
        for (int o = 0; o < OPS; o++) { v[o] = expf(v[o] - mx); s += v[o]; }
        float inv = 1.0f / s;
        for (int o = 0; o < OPS; o++) out[b * OPS + o] = v[o] * inv;
    }
}

// ---------------- launch ----------------
extern "C" void kernel_launch(void* const* d_in, const int* in_sizes, int n_in,
                              void* d_out, int out_size) {
    const int*   node_types = (const int*)d_in[0];
    const float* node_args  = (const float*)d_in[1];
    const float* validity   = (const float*)d_in[2];
    const float* emb_table  = (const float*)d_in[3];
    const float* W_ih       = (const float*)d_in[4];
    const float* W_hh       = (const float*)d_in[5];
    const float* b_ih       = (const float*)d_in[6];
    const float* b_hh       = (const float*)d_in[7];
    const float* W1         = (const float*)d_in[8];
    const float* b1         = (const float*)d_in[9];
    const float* W2         = (const float*)d_in[10];
    const float* b2         = (const float*)d_in[11];
    float* out = (float*)d_out;

    prep_small_kernel<<<(GG + 255) / 256, 256>>>(W_ih, b_ih, b_hh);
    pack_whh_kernel<<<GG, 256>>>(W_hh);
    compP_kernel<<<dim3(VOCAB, GG / 256), 256>>>(emb_table, W_ih);
    node_meta_kernel<<<(PROC * BATCH + 255) / 256, 256>>>(node_types, node_args, emb_table);

    // level d=8: all children are zero leaves
    leaf_level_kernel<<<BATCH * 256, 128>>>();

    // levels d=7..0
    for (int d = 7; d >= 0; --d) {
        int first = (1 << d) - 1;
        dim3 grid(1 << d, GG / 64);
        level_kernel<<<grid, 256>>>(first);
    }

    head_kernel<<<BATCH, 256>>>(W1, b1, W2, b2, validity, out);
}

// round 3
// speedup vs baseline: 3.8469x; 3.8469x over previous
#include <cuda_runtime.h>
#include <cuda_bf16.h>
#include <math.h>
#include <stdint.h>

// ---------------- problem constants ----------------
#define BATCH 64
#define NN    1023
#define PROC  511
#define HH    512
#define EE    512
#define VOCAB 32
#define OPS   16
#define GG    2048        // packed gates q = 4*h + {i,f,g,o}

// ---------------- GEMM tiling ----------------
#define BM 128            // 2 nodes x 64 batch
#define BN 128
#define BK 64
// smem layout: bf16 tiles with row stride 72 bf16 = 144 B (conflict-free for ldmatrix)
#define TSTRIDE 144
#define OFF_AHI 0
#define OFF_ALO (128 * TSTRIDE)
#define OFF_BHI (2 * 128 * TSTRIDE)
#define OFF_BLO (3 * 128 * TSTRIDE)
#define SMEM_BYTES (4 * 128 * TSTRIDE)   // 73728; C staging (128x132 f32 = 67584) reuses it

// ---------------- device scratch ----------------
__device__ __nv_bfloat16 g_hhi[(size_t)PROC * BATCH * HH];
__device__ __nv_bfloat16 g_hlo[(size_t)PROC * BATCH * HH];
__device__ float g_c[(size_t)PROC * BATCH * HH];
__device__ float g_hroot[BATCH * HH];
__device__ __nv_bfloat16 g_Whi[(size_t)GG * 1024];
__device__ __nv_bfloat16 g_Wlo[(size_t)GG * 1024];
__device__ float g_P[VOCAB * GG];
__device__ float g_biasp[GG];
__device__ float g_wlast[GG];
__device__ int   g_tnode[PROC * BATCH];
__device__ float g_dnode[PROC * BATCH];
__device__ float g_part[32u * 64u * 2048u];   // split-K partials: (ks*count+nl, b, q)

// ---------------- helpers ----------------
__device__ __forceinline__ uint32_t smem_u32(const void* p) {
    uint32_t a;
    asm("{ .reg .u64 t; cvta.to.shared.u64 t, %1; cvt.u32.u64 %0, t; }" : "=r"(a) : "l"(p));
    return a;
}
__device__ __forceinline__ void ldm_x4(uint32_t* d, uint32_t addr) {
    asm volatile("ldmatrix.sync.aligned.m8n8.x4.shared.b16 {%0,%1,%2,%3}, [%4];"
                 : "=r"(d[0]), "=r"(d[1]), "=r"(d[2]), "=r"(d[3]) : "r"(addr));
}
__device__ __forceinline__ void mma_bf16(float* c, const uint32_t* a, const uint32_t* b) {
    asm volatile(
        "mma.sync.aligned.m16n8k16.row.col.f32.bf16.bf16.f32 "
        "{%0,%1,%2,%3}, {%4,%5,%6,%7}, {%8,%9}, {%0,%1,%2,%3};"
        : "+f"(c[0]), "+f"(c[1]), "+f"(c[2]), "+f"(c[3])
        : "r"(a[0]), "r"(a[1]), "r"(a[2]), "r"(a[3]), "r"(b[0]), "r"(b[1]));
}
__device__ __forceinline__ float sigmoidf(float x) { return 1.0f / (1.0f + expf(-x)); }
__device__ __forceinline__ int packed_row(int q) { return (q & 3) * 1024 + (q >> 2); }

// per-cell LSTM from raw gate sums (one h index, 4 gates)
__device__ __forceinline__ void lstm_cell(float4 g, int t, float dd, int q, float c0,
                                          float& hn, float& cn) {
    float4 pv = *(const float4*)&g_P[t * GG + q];
    float4 wl = *(const float4*)&g_wlast[q];
    float4 bp = *(const float4*)&g_biasp[q];
    float gi = g.x + pv.x + dd * wl.x + bp.x;
    float gf = g.y + pv.y + dd * wl.y + bp.y;
    float gg = g.z + pv.z + dd * wl.z + bp.z;
    float go = g.w + pv.w + dd * wl.w + bp.w;
    cn = sigmoidf(gf) * c0 + sigmoidf(gi) * tanhf(gg);
    hn = sigmoidf(go) * tanhf(cn);
}

// ---------------- prep kernels ----------------
__global__ void prep_small_kernel(const float* __restrict__ W_ih,
                                  const float* __restrict__ b_ih,
                                  const float* __restrict__ b_hh) {
    int q = blockIdx.x * blockDim.x + threadIdx.x;
    if (q >= GG) return;
    int r = packed_row(q);
    g_biasp[q] = b_ih[r] + b_hh[r];
    g_wlast[q] = W_ih[(size_t)r * EE + (EE - 1)];
}

__global__ void conv_whh_kernel(const float* __restrict__ W_hh) {
    int q = blockIdx.x;
    int r = packed_row(q);
    for (int k = threadIdx.x; k < 1024; k += 256) {
        float v = W_hh[(size_t)r * 1024 + k];
        __nv_bfloat16 hi = __float2bfloat16(v);
        g_Whi[(size_t)q * 1024 + k] = hi;
        g_Wlo[(size_t)q * 1024 + k] = __float2bfloat16(v - __bfloat162float(hi));
    }
}

__global__ void compP_kernel(const float* __restrict__ emb_table,
                             const float* __restrict__ W_ih) {
    __shared__ float se[EE];
    int t = blockIdx.x;
    for (int i = threadIdx.x; i < EE; i += blockDim.x)
        se[i] = emb_table[(size_t)t * EE + i];
    __syncthreads();
    int q = blockIdx.y * blockDim.x + threadIdx.x;
    int r = packed_row(q);
    const float4* w = (const float4*)(W_ih + (size_t)r * EE);
    const float4* s4 = (const float4*)se;
    float acc = 0.f;
#pragma unroll 8
    for (int e = 0; e < EE / 4; e++) {
        float4 a = s4[e], b = w[e];
        acc += a.x * b.x + a.y * b.y + a.z * b.z + a.w * b.w;
    }
    g_P[t * GG + q] = acc;
}

__global__ void node_meta_kernel(const int* __restrict__ node_types,
                                 const float* __restrict__ node_args,
                                 const float* __restrict__ emb_table) {
    int i = blockIdx.x * blockDim.x + threadIdx.x;
    if (i >= PROC * BATCH) return;
    int node = i >> 6;
    int b = i & 63;
    int t = node_types[(size_t)b * NN + node];
    g_tnode[i] = t;
    float d = 0.f;
    if (t <= 1)
        d = node_args[(size_t)b * NN + node] - emb_table[(size_t)t * EE + (EE - 1)];
    g_dnode[i] = d;
}

// ---------------- leaf level (d=8): zero children ----------------
__global__ void leaf_level_kernel() {
    int node = 255 + blockIdx.x;
    int b = threadIdx.x;
    int h0 = blockIdx.y * 64;
    int ni = node * BATCH + b;
    int t = g_tnode[ni];
    float dd = g_dnode[ni];
    size_t base = ((size_t)node * BATCH + b) * HH;
    for (int g8 = 0; g8 < 8; g8++) {
        int hb = h0 + g8 * 8;
        __nv_bfloat16 hhi8[8], hlo8[8];
        float c8[8];
#pragma unroll
        for (int j = 0; j < 8; j++) {
            int q = 4 * (hb + j);
            float4 pv = *(const float4*)&g_P[t * GG + q];
            float4 wl = *(const float4*)&g_wlast[q];
            float4 bp = *(const float4*)&g_biasp[q];
            float gi = pv.x + dd * wl.x + bp.x;
            float gg = pv.z + dd * wl.z + bp.z;
            float go = pv.w + dd * wl.w + bp.w;
            float cn = sigmoidf(gi) * tanhf(gg);
            float hn = sigmoidf(go) * tanhf(cn);
            c8[j] = cn;
            __nv_bfloat16 hi = __float2bfloat16(hn);
            hhi8[j] = hi;
            hlo8[j] = __float2bfloat16(hn - __bfloat162float(hi));
        }
        *(uint4*)&g_hhi[base + hb] = *(uint4*)hhi8;
        *(uint4*)&g_hlo[base + hb] = *(uint4*)hlo8;
        *(float4*)&g_c[base + hb]     = *(float4*)c8;
        *(float4*)&g_c[base + hb + 4] = *(float4*)(c8 + 4);
    }
}

// ---------------- level GEMM: split-bf16 mma.sync + (fused LSTM | split-K partials) ----
__global__ void __launch_bounds__(256, 2) level_mma_kernel(int first, int count, int ksplit) {
    extern __shared__ char smem[];
    uint32_t sb = smem_u32(smem);
    float* Cs = (float*)smem;

    const int tid = threadIdx.x;
    const int lane = tid & 31;
    const int wid = tid >> 5;
    const int warp_m = wid & 3;   // 4 in M
    const int warp_n = wid >> 2;  // 2 in N

    const int p = blockIdx.x;
    const int n0 = first + 2 * p;
    const int n1 = (n0 + 1 <= first + count - 1) ? n0 + 1 : n0;
    const int q0 = blockIdx.y * BN;
    const int ks = blockIdx.z;
    const int chunks = 16 / ksplit;
    const int kc0 = ks * chunks;

    float acc[2][8][4];
#pragma unroll
    for (int mt = 0; mt < 2; mt++)
#pragma unroll
        for (int nt = 0; nt < 8; nt++)
#pragma unroll
            for (int i = 0; i < 4; i++) acc[mt][nt][i] = 0.f;

    // precompute per-thread load indices
    const int lr = tid >> 1;            // used pattern: i = tid + it*256 -> r = i>>3, cg = i&7
    (void)lr;

    for (int kc = kc0; kc < kc0 + chunks; kc++) {
        const int k0 = kc * BK;
        const int childbase = (k0 < 512) ? 1 : 2;
        const int kk = k0 & 511;

        // ---- load A/B (hi+lo) into padded smem ----
#pragma unroll
        for (int it = 0; it < 4; it++) {
            int i = tid + it * 256;             // 0..1023
            int r = i >> 3, cg = i & 7;
            int node = (r < 64) ? n0 : n1;
            int b = r & 63;
            size_t asrc = ((size_t)(2 * node + childbase) * BATCH + b) * HH + kk + cg * 8;
            size_t bsrc = (size_t)(q0 + r) * 1024 + k0 + cg * 8;
            uint32_t so = (uint32_t)(r * TSTRIDE + cg * 16);
            *(uint4*)(smem + OFF_AHI + so) = *(const uint4*)(g_hhi + asrc);
            *(uint4*)(smem + OFF_ALO + so) = *(const uint4*)(g_hlo + asrc);
            *(uint4*)(smem + OFF_BHI + so) = *(const uint4*)(g_Whi + bsrc);
            *(uint4*)(smem + OFF_BLO + so) = *(const uint4*)(g_Wlo + bsrc);
        }
        __syncthreads();

        // ---- compute: 4 k16 steps ----
        const uint32_t a_off = (uint32_t)((warp_m * 32 + (lane & 15)) * TSTRIDE + (lane >> 4) * 16);
        const uint32_t b_off = (uint32_t)((warp_n * 64 + ((lane >> 4) << 3) + (lane & 7)) * TSTRIDE
                                          + (((lane >> 3) & 1) << 4));
#pragma unroll
        for (int kt = 0; kt < 4; kt++) {
            uint32_t ah[2][4], al[2][4];
            ldm_x4(ah[0], sb + OFF_AHI + a_off + kt * 32);
            ldm_x4(ah[1], sb + OFF_AHI + a_off + kt * 32 + 16 * TSTRIDE);
            ldm_x4(al[0], sb + OFF_ALO + a_off + kt * 32);
            ldm_x4(al[1], sb + OFF_ALO + a_off + kt * 32 + 16 * TSTRIDE);
#pragma unroll
            for (int ng = 0; ng < 4; ng++) {
                uint32_t bh[4], bl[4];
                ldm_x4(bh, sb + OFF_BHI + b_off + kt * 32 + ng * 16 * TSTRIDE);
                ldm_x4(bl, sb + OFF_BLO + b_off + kt * 32 + ng * 16 * TSTRIDE);
#pragma unroll
                for (int half = 0; half < 2; half++) {
                    int nt = ng * 2 + half;
#pragma unroll
                    for (int mt = 0; mt < 2; mt++) {
                        mma_bf16(acc[mt][nt], ah[mt], bh + 2 * half);
                        mma_bf16(acc[mt][nt], al[mt], bh + 2 * half);
                        mma_bf16(acc[mt][nt], ah[mt], bl + 2 * half);
                    }
                }
            }
        }
        __syncthreads();
    }

    // ---- stage C tile to smem (128 x 132 f32) ----
#pragma unroll
    for (int mt = 0; mt < 2; mt++)
#pragma unroll
        for (int nt = 0; nt < 8; nt++) {
            int r = warp_m * 32 + mt * 16 + (lane >> 2);
            int c = warp_n * 64 + nt * 8 + (lane & 3) * 2;
            *(float2*)&Cs[r * 132 + c]       = make_float2(acc[mt][nt][0], acc[mt][nt][1]);
            *(float2*)&Cs[(r + 8) * 132 + c] = make_float2(acc[mt][nt][2], acc[mt][nt][3]);
        }
    __syncthreads();

    if (ksplit == 1) {
        // fused LSTM epilogue: 128 rows x 32 h-cells
        for (int idx = tid; idx < 128 * 32; idx += 256) {
            int r = idx >> 5, hg = idx & 31;
            if (r >= 64 && n1 == n0) continue;
            int node = (r < 64) ? n0 : n1;
            int b = r & 63;
            int ni = node * BATCH + b;
            int t = g_tnode[ni];
            float dd = g_dnode[ni];
            int hidx = (q0 >> 2) + hg;
            int q = q0 + hg * 4;
            float c0 = g_c[((size_t)(2 * node + 1) * BATCH + b) * HH + hidx];
            float4 g = *(const float4*)&Cs[r * 132 + hg * 4];
            float hn, cn;
            lstm_cell(g, t, dd, q, c0, hn, cn);
            size_t o = ((size_t)node * BATCH + b) * HH + hidx;
            __nv_bfloat16 hi = __float2bfloat16(hn);
            g_hhi[o] = hi;
            g_hlo[o] = __float2bfloat16(hn - __bfloat162float(hi));
            g_c[o] = cn;
            if (node == 0) g_hroot[b * HH + hidx] = hn;
        }
    } else {
        // write partial tile to g_part, slice-major
        for (int i = tid; i < 128 * 32; i += 256) {
            int r = i >> 5, c4 = i & 31;
            int nl = 2 * p + (r >= 64 ? 1 : 0);
            if (nl >= count) continue;
            int b = r & 63;
            size_t dst = (((size_t)(ks * count + nl) * 64 + b) * 2048) + q0 + c4 * 4;
            *(float4*)&g_part[dst] = *(const float4*)&Cs[r * 132 + c4 * 4];
        }
    }
}

// ---------------- split-K reduction + LSTM ----------------
__global__ void level_reduce_kernel(int first, int count, int ksplit) {
    int nl = blockIdx.x;
    int node = first + nl;
    int q0 = blockIdx.y * BN;
    int tid = threadIdx.x;
    for (int idx = tid; idx < 64 * 32; idx += 256) {
        int b = idx >> 5, hg = idx & 31;
        int q = q0 + hg * 4;
        int hidx = (q0 >> 2) + hg;
        float4 s = make_float4(0.f, 0.f, 0.f, 0.f);
        for (int ks = 0; ks < ksplit; ks++) {
            const float4 v = *(const float4*)&g_part[(((size_t)(ks * count + nl) * 64 + b) * 2048) + q];
            s.x += v.x; s.y += v.y; s.z += v.z; s.w += v.w;
        }
        int ni = node * BATCH + b;
        int t = g_tnode[ni];
        float dd = g_dnode[ni];
        float c0 = g_c[((size_t)(2 * node + 1) * BATCH + b) * HH + hidx];
        float hn, cn;
        lstm_cell(s, t, dd, q, c0, hn, cn);
        size_t o = ((size_t)node * BATCH + b) * HH + hidx;
        __nv_bfloat16 hi = __float2bfloat16(hn);
        g_hhi[o] = hi;
        g_hlo[o] = __float2bfloat16(hn - __bfloat162float(hi));
        g_c[o] = cn;
        if (node == 0) g_hroot[b * HH + hidx] = hn;
    }
}

// ---------------- output head ----------------
__global__ void head_kernel(const float* __restrict__ W1, const float* __restrict__ b1,
                            const float* __restrict__ W2, const float* __restrict__ b2,
                            const float* __restrict__ validity, float* __restrict__ out) {
    int b = blockIdx.x;
    __shared__ float sh[HH];
    __shared__ float sx[HH];
    __shared__ float slog[OPS];
    const float* rh = g_hroot + (size_t)b * HH;
    for (int i = threadIdx.x; i < HH; i += blockDim.x) sh[i] = rh[i];
    __syncthreads();
    for (int j = threadIdx.x; j < HH; j += blockDim.x) {
        float acc = b1[j];
        const float4* w = (const float4*)(W1 + (size_t)j * HH);
        const float4* s4 = (const float4*)sh;
#pragma unroll 8
        for (int e = 0; e < HH / 4; e++) {
            float4 a = s4[e], ww = w[e];
            acc += a.x * ww.x + a.y * ww.y + a.z * ww.z + a.w * ww.w;
        }
        sx[j] = fmaxf(acc, 0.f);
    }
    __syncthreads();
    int warp = threadIdx.x >> 5, lane = threadIdx.x & 31;
    for (int o = warp; o < OPS; o += 8) {
        float acc = 0.f;
        const float* w = W2 + (size_t)o * HH;
        for (int e = lane; e < HH; e += 32) acc += sx[e] * w[e];
#pragma unroll
        for (int off = 16; off; off >>= 1) acc += __shfl_xor_sync(0xffffffff, acc, off);
        if (lane == 0) slog[o] = acc + b2[o] + logf(validity[b * OPS + o]);
    }
    __syncthreads();
    if (threadIdx.x == 0) {
        float mx = -1e30f;
        float v[OPS];
        for (int o = 0; o < OPS; o++) { v[o] = slog[o] / 3.0f; if (v[o] > mx) mx = v[o]; }
        float s = 0.f;
        for (int o = 0; o < OPS; o++) { v[o] = expf(v[o] - mx); s += v[o]; }
        float inv = 1.0f / s;
        for (int o = 0; o < OPS; o++) out[b * OPS + o] = v[o] * inv;
    }
}

// ---------------- launch ----------------
extern "C" void kernel_launch(void* const* d_in, const int* in_sizes, int n_in,
                              void* d_out, int out_size) {
    const int*   node_types = (const int*)d_in[0];
    const float* node_args  = (const float*)d_in[1];
    const float* validity   = (const float*)d_in[2];
    const float* emb_table  = (const float*)d_in[3];
    const float* W_ih       = (const float*)d_in[4];
    const float* W_hh       = (const float*)d_in[5];
    const float* b_ih       = (const float*)d_in[6];
    const float* b_hh       = (const float*)d_in[7];
    const float* W1         = (const float*)d_in[8];
    const float* b1         = (const float*)d_in[9];
    const float* W2         = (const float*)d_in[10];
    const float* b2         = (const float*)d_in[11];
    float* out = (float*)d_out;

    static bool attr_set = false;
    if (!attr_set) {
        cudaFuncSetAttribute(level_mma_kernel,
                             cudaFuncAttributeMaxDynamicSharedMemorySize, SMEM_BYTES);
        attr_set = true;
    }

    prep_small_kernel<<<(GG + 255) / 256, 256>>>(W_ih, b_ih, b_hh);
    conv_whh_kernel<<<GG, 256>>>(W_hh);
    compP_kernel<<<dim3(VOCAB, GG / 256), 256>>>(emb_table, W_ih);
    node_meta_kernel<<<(PROC * BATCH + 255) / 256, 256>>>(node_types, node_args, emb_table);

    leaf_level_kernel<<<dim3(256, 8), 64>>>();

    for (int d = 7; d >= 0; --d) {
        int first = (1 << d) - 1;
        int count = 1 << d;
        int sk = (d >= 5) ? 1 : (d == 4 ? 2 : (d == 3 ? 4 : 8));
        dim3 grid((count + 1) / 2, GG / BN, sk);
        level_mma_kernel<<<grid, 256, SMEM_BYTES>>>(first, count, sk);
        if (sk > 1)
            level_reduce_kernel<<<dim3(count, GG / BN), 256>>>(first, count, sk);
    }

    head_kernel<<<BATCH, 256>>>(W1, b1, W2, b2, validity, out);
}

// round 4
// speedup vs baseline: 4.7344x; 1.2307x over previous
#include <cuda_runtime.h>
#include <cuda_bf16.h>
#include <math.h>
#include <stdint.h>

// ---------------- problem constants ----------------
#define BATCH 64
#define NN    1023
#define PROC  511
#define HH    512
#define EE    512
#define VOCAB 32
#define OPS   16
#define GG    2048        // packed gates q = 4*h + {i,f,g,o}

// ---------------- GEMM tiling ----------------
#define BM 128            // 2 nodes x 64 batch
#define BN 128
#define BK 64
// smem: bf16 tiles, row stride 72 bf16 = 144 B (ldmatrix conflict-free)
#define TSTRIDE 144
#define OFF_AHI 0
#define OFF_ALO 18432
#define OFF_BHI 36864
#define ST_SZ   55296
#define SMEM_BYTES (2 * ST_SZ)   // 110592; C staging (128x132 f32 = 67584) reuses it

// ---------------- device scratch ----------------
__device__ __nv_bfloat16 g_hhi[(size_t)PROC * BATCH * HH];
__device__ __nv_bfloat16 g_hlo[(size_t)PROC * BATCH * HH];
__device__ float g_c[(size_t)PROC * BATCH * HH];
__device__ float g_hroot[BATCH * HH];
__device__ __nv_bfloat16 g_Whi[(size_t)GG * 1024];
__device__ float g_P[VOCAB * GG];
__device__ float g_biasp[GG];
__device__ float g_wlast[GG];
__device__ int   g_tnode[PROC * BATCH];
__device__ float g_dnode[PROC * BATCH];
__device__ float g_part[32u * 64u * 2048u];   // split-K partials

// ---------------- helpers ----------------
__device__ __forceinline__ uint32_t smem_u32(const void* p) {
    uint32_t a;
    asm("{ .reg .u64 t; cvta.to.shared.u64 t, %1; cvt.u32.u64 %0, t; }" : "=r"(a) : "l"(p));
    return a;
}
__device__ __forceinline__ void cp16(uint32_t dst, const void* src) {
    asm volatile("cp.async.cg.shared.global [%0], [%1], 16;" :: "r"(dst), "l"(src));
}
#define CP_COMMIT() asm volatile("cp.async.commit_group;" ::: "memory")
template <int N>
__device__ __forceinline__ void cp_wait() {
    asm volatile("cp.async.wait_group %0;" :: "n"(N) : "memory");
}
__device__ __forceinline__ void ldm_x4(uint32_t* d, uint32_t addr) {
    asm volatile("ldmatrix.sync.aligned.m8n8.x4.shared.b16 {%0,%1,%2,%3}, [%4];"
                 : "=r"(d[0]), "=r"(d[1]), "=r"(d[2]), "=r"(d[3]) : "r"(addr));
}
__device__ __forceinline__ void mma_bf16(float* c, const uint32_t* a, const uint32_t* b) {
    asm volatile(
        "mma.sync.aligned.m16n8k16.row.col.f32.bf16.bf16.f32 "
        "{%0,%1,%2,%3}, {%4,%5,%6,%7}, {%8,%9}, {%0,%1,%2,%3};"
        : "+f"(c[0]), "+f"(c[1]), "+f"(c[2]), "+f"(c[3])
        : "r"(a[0]), "r"(a[1]), "r"(a[2]), "r"(a[3]), "r"(b[0]), "r"(b[1]));
}
__device__ __forceinline__ float sigmoidf(float x) { return 1.0f / (1.0f + expf(-x)); }
__device__ __forceinline__ int packed_row(int q) { return (q & 3) * 1024 + (q >> 2); }

__device__ __forceinline__ void lstm_cell(float4 g, int t, float dd, int q, float c0,
                                          float& hn, float& cn) {
    float4 pv = *(const float4*)&g_P[t * GG + q];
    float4 wl = *(const float4*)&g_wlast[q];
    float4 bp = *(const float4*)&g_biasp[q];
    float gi = g.x + pv.x + dd * wl.x + bp.x;
    float gf = g.y + pv.y + dd * wl.y + bp.y;
    float gg = g.z + pv.z + dd * wl.z + bp.z;
    float go = g.w + pv.w + dd * wl.w + bp.w;
    cn = sigmoidf(gf) * c0 + sigmoidf(gi) * tanhf(gg);
    hn = sigmoidf(go) * tanhf(cn);
}

// ---------------- prep kernels ----------------
__global__ void prep_small_kernel(const float* __restrict__ W_ih,
                                  const float* __restrict__ b_ih,
                                  const float* __restrict__ b_hh) {
    int q = blockIdx.x * blockDim.x + threadIdx.x;
    if (q >= GG) return;
    int r = packed_row(q);
    g_biasp[q] = b_ih[r] + b_hh[r];
    g_wlast[q] = W_ih[(size_t)r * EE + (EE - 1)];
}

__global__ void conv_whh_kernel(const float* __restrict__ W_hh) {
    int q = blockIdx.x;
    int r = packed_row(q);
    for (int k = threadIdx.x; k < 1024; k += 256)
        g_Whi[(size_t)q * 1024 + k] = __float2bfloat16(W_hh[(size_t)r * 1024 + k]);
}

__global__ void compP_kernel(const float* __restrict__ emb_table,
                             const float* __restrict__ W_ih) {
    __shared__ float se[EE];
    int t = blockIdx.x;
    for (int i = threadIdx.x; i < EE; i += blockDim.x)
        se[i] = emb_table[(size_t)t * EE + i];
    __syncthreads();
    int q = blockIdx.y * blockDim.x + threadIdx.x;
    int r = packed_row(q);
    const float4* w = (const float4*)(W_ih + (size_t)r * EE);
    const float4* s4 = (const float4*)se;
    float acc = 0.f;
#pragma unroll 8
    for (int e = 0; e < EE / 4; e++) {
        float4 a = s4[e], b = w[e];
        acc += a.x * b.x + a.y * b.y + a.z * b.z + a.w * b.w;
    }
    g_P[t * GG + q] = acc;
}

__global__ void node_meta_kernel(const int* __restrict__ node_types,
                                 const float* __restrict__ node_args,
                                 const float* __restrict__ emb_table) {
    int i = blockIdx.x * blockDim.x + threadIdx.x;
    if (i >= PROC * BATCH) return;
    int node = i >> 6;
    int b = i & 63;
    int t = node_types[(size_t)b * NN + node];
    g_tnode[i] = t;
    float d = 0.f;
    if (t <= 1)
        d = node_args[(size_t)b * NN + node] - emb_table[(size_t)t * EE + (EE - 1)];
    g_dnode[i] = d;
}

// ---------------- leaf level (d=8): zero children ----------------
__global__ void leaf_level_kernel() {
    int node = 255 + blockIdx.x;
    int b = threadIdx.x;
    int h0 = blockIdx.y * 64;
    int ni = node * BATCH + b;
    int t = g_tnode[ni];
    float dd = g_dnode[ni];
    size_t base = ((size_t)node * BATCH + b) * HH;
    for (int g8 = 0; g8 < 8; g8++) {
        int hb = h0 + g8 * 8;
        __nv_bfloat16 hhi8[8], hlo8[8];
        float c8[8];
#pragma unroll
        for (int j = 0; j < 8; j++) {
            int q = 4 * (hb + j);
            float4 pv = *(const float4*)&g_P[t * GG + q];
            float4 wl = *(const float4*)&g_wlast[q];
            float4 bp = *(const float4*)&g_biasp[q];
            float gi = pv.x + dd * wl.x + bp.x;
            float gg = pv.z + dd * wl.z + bp.z;
            float go = pv.w + dd * wl.w + bp.w;
            float cn = sigmoidf(gi) * tanhf(gg);
            float hn = sigmoidf(go) * tanhf(cn);
            c8[j] = cn;
            __nv_bfloat16 hi = __float2bfloat16(hn);
            hhi8[j] = hi;
            hlo8[j] = __float2bfloat16(hn - __bfloat162float(hi));
        }
        *(uint4*)&g_hhi[base + hb] = *(uint4*)hhi8;
        *(uint4*)&g_hlo[base + hb] = *(uint4*)hlo8;
        *(float4*)&g_c[base + hb]     = *(float4*)c8;
        *(float4*)&g_c[base + hb + 4] = *(float4*)(c8 + 4);
    }
}

// ---------------- level GEMM: 2-product split-bf16, cp.async double-buffered ----------
__global__ void __launch_bounds__(256, 2) level_mma_kernel(int first, int count, int ksplit) {
    extern __shared__ char smem[];
    uint32_t sb = smem_u32(smem);
    float* Cs = (float*)smem;

    const int tid = threadIdx.x;
    const int lane = tid & 31;
    const int wid = tid >> 5;
    const int warp_m = wid & 3;
    const int warp_n = wid >> 2;

    const int p = blockIdx.x;
    const int n0 = first + 2 * p;
    const int n1 = (n0 + 1 <= first + count - 1) ? n0 + 1 : n0;
    const int q0 = blockIdx.y * BN;
    const int ks = blockIdx.z;
    const int chunks = 16 / ksplit;
    const int kc0 = ks * chunks;
    const int kcE = kc0 + chunks;

    // per-thread load coordinates (4 rows of 8 cg each)
    int lrow[4], lcg[4];
#pragma unroll
    for (int it = 0; it < 4; it++) {
        int i = tid + it * 256;
        lrow[it] = i >> 3;
        lcg[it] = i & 7;
    }

    float acc[2][8][4];
#pragma unroll
    for (int mt = 0; mt < 2; mt++)
#pragma unroll
        for (int nt = 0; nt < 8; nt++)
#pragma unroll
            for (int i = 0; i < 4; i++) acc[mt][nt][i] = 0.f;

    // issue loads for chunk kc into buffer buf
    auto issue = [&](int kc, int buf) {
        const int k0 = kc * BK;
        const int childbase = (k0 < 512) ? 1 : 2;
        const int kk = k0 & 511;
        const uint32_t base = sb + buf * ST_SZ;
#pragma unroll
        for (int it = 0; it < 4; it++) {
            int r = lrow[it], cg = lcg[it];
            int node = (r < 64) ? n0 : n1;
            int b = r & 63;
            size_t asrc = ((size_t)(2 * node + childbase) * BATCH + b) * HH + kk + cg * 8;
            size_t bsrc = (size_t)(q0 + r) * 1024 + k0 + cg * 8;
            uint32_t so = (uint32_t)(r * TSTRIDE + cg * 16);
            cp16(base + OFF_AHI + so, g_hhi + asrc);
            cp16(base + OFF_ALO + so, g_hlo + asrc);
            cp16(base + OFF_BHI + so, g_Whi + bsrc);
        }
    };

    issue(kc0, 0);
    CP_COMMIT();

    for (int kc = kc0; kc < kcE; kc++) {
        const int buf = (kc - kc0) & 1;
        if (kc + 1 < kcE) {
            issue(kc + 1, buf ^ 1);
            CP_COMMIT();
            cp_wait<1>();
        } else {
            cp_wait<0>();
        }
        __syncthreads();

        const uint32_t bufb = sb + buf * ST_SZ;
        const uint32_t a_off = (uint32_t)((warp_m * 32 + (lane & 15)) * TSTRIDE + (lane >> 4) * 16);
        const uint32_t b_off = (uint32_t)((warp_n * 64 + ((lane >> 4) << 3) + (lane & 7)) * TSTRIDE
                                          + (((lane >> 3) & 1) << 4));
#pragma unroll
        for (int kt = 0; kt < 4; kt++) {
            uint32_t ah[2][4], al[2][4];
            ldm_x4(ah[0], bufb + OFF_AHI + a_off + kt * 32);
            ldm_x4(ah[1], bufb + OFF_AHI + a_off + kt * 32 + 16 * TSTRIDE);
            ldm_x4(al[0], bufb + OFF_ALO + a_off + kt * 32);
            ldm_x4(al[1], bufb + OFF_ALO + a_off + kt * 32 + 16 * TSTRIDE);
#pragma unroll
            for (int ng = 0; ng < 4; ng++) {
                uint32_t bh[4];
                ldm_x4(bh, bufb + OFF_BHI + b_off + kt * 32 + ng * 16 * TSTRIDE);
#pragma unroll
                for (int half = 0; half < 2; half++) {
                    int nt = ng * 2 + half;
#pragma unroll
                    for (int mt = 0; mt < 2; mt++) {
                        mma_bf16(acc[mt][nt], ah[mt], bh + 2 * half);
                        mma_bf16(acc[mt][nt], al[mt], bh + 2 * half);
                    }
                }
            }
        }
        __syncthreads();
    }

    // ---- stage C to smem (128 x 132 f32) ----
#pragma unroll
    for (int mt = 0; mt < 2; mt++)
#pragma unroll
        for (int nt = 0; nt < 8; nt++) {
            int r = warp_m * 32 + mt * 16 + (lane >> 2);
            int c = warp_n * 64 + nt * 8 + (lane & 3) * 2;
            *(float2*)&Cs[r * 132 + c]       = make_float2(acc[mt][nt][0], acc[mt][nt][1]);
            *(float2*)&Cs[(r + 8) * 132 + c] = make_float2(acc[mt][nt][2], acc[mt][nt][3]);
        }
    __syncthreads();

    if (ksplit == 1) {
        for (int idx = tid; idx < 128 * 32; idx += 256) {
            int r = idx >> 5, hg = idx & 31;
            if (r >= 64 && n1 == n0) continue;
            int node = (r < 64) ? n0 : n1;
            int b = r & 63;
            int ni = node * BATCH + b;
            int t = g_tnode[ni];
            float dd = g_dnode[ni];
            int hidx = (q0 >> 2) + hg;
            int q = q0 + hg * 4;
            float c0 = g_c[((size_t)(2 * node + 1) * BATCH + b) * HH + hidx];
            float4 g = *(const float4*)&Cs[r * 132 + hg * 4];
            float hn, cn;
            lstm_cell(g, t, dd, q, c0, hn, cn);
            size_t o = ((size_t)node * BATCH + b) * HH + hidx;
            __nv_bfloat16 hi = __float2bfloat16(hn);
            g_hhi[o] = hi;
            g_hlo[o] = __float2bfloat16(hn - __bfloat162float(hi));
            g_c[o] = cn;
            if (node == 0) g_hroot[b * HH + hidx] = hn;
        }
    } else {
        for (int i = tid; i < 128 * 32; i += 256) {
            int r = i >> 5, c4 = i & 31;
            int nl = 2 * p + (r >= 64 ? 1 : 0);
            if (nl >= count) continue;
            int b = r & 63;
            size_t dst = (((size_t)(ks * count + nl) * 64 + b) * 2048) + q0 + c4 * 4;
            *(float4*)&g_part[dst] = *(const float4*)&Cs[r * 132 + c4 * 4];
        }
    }
}

// ---------------- split-K reduction + LSTM ----------------
__global__ void level_reduce_kernel(int first, int count, int ksplit) {
    int nl = blockIdx.x;
    int node = first + nl;
    int q0 = blockIdx.y * BN;
    int tid = threadIdx.x;
    for (int idx = tid; idx < 64 * 32; idx += 256) {
        int b = idx >> 5, hg = idx & 31;
        int q = q0 + hg * 4;
        int hidx = (q0 >> 2) + hg;
        float4 s = make_float4(0.f, 0.f, 0.f, 0.f);
        for (int ks = 0; ks < ksplit; ks++) {
            const float4 v = *(const float4*)&g_part[(((size_t)(ks * count + nl) * 64 + b) * 2048) + q];
            s.x += v.x; s.y += v.y; s.z += v.z; s.w += v.w;
        }
        int ni = node * BATCH + b;
        int t = g_tnode[ni];
        float dd = g_dnode[ni];
        float c0 = g_c[((size_t)(2 * node + 1) * BATCH + b) * HH + hidx];
        float hn, cn;
        lstm_cell(s, t, dd, q, c0, hn, cn);
        size_t o = ((size_t)node * BATCH + b) * HH + hidx;
        __nv_bfloat16 hi = __float2bfloat16(hn);
        g_hhi[o] = hi;
        g_hlo[o] = __float2bfloat16(hn - __bfloat162float(hi));
        g_c[o] = cn;
        if (node == 0) g_hroot[b * HH + hidx] = hn;
    }
}

// ---------------- output head ----------------
__global__ void head_kernel(const float* __restrict__ W1, const float* __restrict__ b1,
                            const float* __restrict__ W2, const float* __restrict__ b2,
                            const float* __restrict__ validity, float* __restrict__ out) {
    int b = blockIdx.x;
    __shared__ float sh[HH];
    __shared__ float sx[HH];
    __shared__ float slog[OPS];
    const float* rh = g_hroot + (size_t)b * HH;
    for (int i = threadIdx.x; i < HH; i += blockDim.x) sh[i] = rh[i];
    __syncthreads();
    for (int j = threadIdx.x; j < HH; j += blockDim.x) {
        float acc = b1[j];
        const float4* w = (const float4*)(W1 + (size_t)j * HH);
        const float4* s4 = (const float4*)sh;
#pragma unroll 8
        for (int e = 0; e < HH / 4; e++) {
            float4 a = s4[e], ww = w[e];
            acc += a.x * ww.x + a.y * ww.y + a.z * ww.z + a.w * ww.w;
        }
        sx[j] = fmaxf(acc, 0.f);
    }
    __syncthreads();
    int warp = threadIdx.x >> 5, lane = threadIdx.x & 31;
    for (int o = warp; o < OPS; o += 8) {
        float acc = 0.f;
        const float* w = W2 + (size_t)o * HH;
        for (int e = lane; e < HH; e += 32) acc += sx[e] * w[e];
#pragma unroll
        for (int off = 16; off; off >>= 1) acc += __shfl_xor_sync(0xffffffff, acc, off);
        if (lane == 0) slog[o] = acc + b2[o] + logf(validity[b * OPS + o]);
    }
    __syncthreads();
    if (threadIdx.x == 0) {
        float mx = -1e30f;
        float v[OPS];
        for (int o = 0; o < OPS; o++) { v[o] = slog[o] / 3.0f; if (v[o] > mx) mx = v[o]; }
        float s = 0.f;
        for (int o = 0; o < OPS; o++) { v[o] = expf(v[o] - mx); s += v[o]; }
        float inv = 1.0f / s;
        for (int o = 0; o < OPS; o++) out[b * OPS + o] = v[o] * inv;
    }
}

// ---------------- launch ----------------
extern "C" void kernel_launch(void* const* d_in, const int* in_sizes, int n_in,
                              void* d_out, int out_size) {
    const int*   node_types = (const int*)d_in[0];
    const float* node_args  = (const float*)d_in[1];
    const float* validity   = (const float*)d_in[2];
    const float* emb_table  = (const float*)d_in[3];
    const float* W_ih       = (const float*)d_in[4];
    const float* W_hh       = (const float*)d_in[5];
    const float* b_ih       = (const float*)d_in[6];
    const float* b_hh       = (const float*)d_in[7];
    const float* W1         = (const float*)d_in[8];
    const float* b1         = (const float*)d_in[9];
    const float* W2         = (const float*)d_in[10];
    const float* b2         = (const float*)d_in[11];
    float* out = (float*)d_out;

    static bool attr_set = false;
    if (!attr_set) {
        cudaFuncSetAttribute(level_mma_kernel,
                             cudaFuncAttributeMaxDynamicSharedMemorySize, SMEM_BYTES);
        attr_set = true;
    }

    prep_small_kernel<<<(GG + 255) / 256, 256>>>(W_ih, b_ih, b_hh);
    conv_whh_kernel<<<GG, 256>>>(W_hh);
    compP_kernel<<<dim3(VOCAB, GG / 256), 256>>>(emb_table, W_ih);
    node_meta_kernel<<<(PROC * BATCH + 255) / 256, 256>>>(node_types, node_args, emb_table);

    leaf_level_kernel<<<dim3(256, 8), 64>>>();

    for (int d = 7; d >= 0; --d) {
        int first = (1 << d) - 1;
        int count = 1 << d;
        int sk = (d >= 5) ? 1 : (d == 4 ? 2 : (d == 3 ? 4 : 8));
        dim3 grid((count + 1) / 2, GG / BN, sk);
        level_mma_kernel<<<grid, 256, SMEM_BYTES>>>(first, count, sk);
        if (sk > 1)
            level_reduce_kernel<<<dim3(count, GG / BN), 256>>>(first, count, sk);
    }

    head_kernel<<<BATCH, 256>>>(W1, b1, W2, b2, validity, out);
}

// round 5
// speedup vs baseline: 6.3260x; 1.3362x over previous
#include <cuda_runtime.h>
#include <cuda_bf16.h>
#include <math.h>
#include <stdint.h>

// ---------------- problem constants ----------------
#define BATCH 64
#define NN    1023
#define PROC  511
#define HH    512
#define EE    512
#define VOCAB 32
#define OPS   16
#define GG    2048        // packed gates q = 4*h + {i,f,g,o}

// ---------------- GEMM tiling ----------------
#define BM 128            // 2 nodes x 64 batch
#define BN 128
#define BK 64
// smem: bf16 tiles, row stride 72 bf16 = 144 B (ldmatrix conflict-free)
#define TSTRIDE 144
#define OFF_AHI 0
#define OFF_BHI 18432
#define ST_SZ   36864
#define SMEM_BYTES (2 * ST_SZ)   // 73728; C staging (128x132 f32 = 67584) fits

// ---------------- device scratch ----------------
__device__ __nv_bfloat16 g_hhi[(size_t)PROC * BATCH * HH];
__device__ float g_c[(size_t)PROC * BATCH * HH];
__device__ float g_hroot[BATCH * HH];
__device__ __nv_bfloat16 g_Whi[(size_t)GG * 1024];
__device__ float g_P[VOCAB * GG];
__device__ float g_biasp[GG];
__device__ float g_wlast[GG];
__device__ int   g_tnode[PROC * BATCH];
__device__ float g_dnode[PROC * BATCH];
__device__ float g_part[32u * 64u * 2048u];   // split-K partials

// ---------------- helpers ----------------
__device__ __forceinline__ uint32_t smem_u32(const void* p) {
    uint32_t a;
    asm("{ .reg .u64 t; cvta.to.shared.u64 t, %1; cvt.u32.u64 %0, t; }" : "=r"(a) : "l"(p));
    return a;
}
__device__ __forceinline__ void cp16(uint32_t dst, const void* src) {
    asm volatile("cp.async.cg.shared.global [%0], [%1], 16;" :: "r"(dst), "l"(src));
}
#define CP_COMMIT() asm volatile("cp.async.commit_group;" ::: "memory")
template <int N>
__device__ __forceinline__ void cp_wait() {
    asm volatile("cp.async.wait_group %0;" :: "n"(N) : "memory");
}
__device__ __forceinline__ void ldm_x4(uint32_t* d, uint32_t addr) {
    asm volatile("ldmatrix.sync.aligned.m8n8.x4.shared.b16 {%0,%1,%2,%3}, [%4];"
                 : "=r"(d[0]), "=r"(d[1]), "=r"(d[2]), "=r"(d[3]) : "r"(addr));
}
__device__ __forceinline__ void mma_bf16(float* c, const uint32_t* a, const uint32_t* b) {
    asm volatile(
        "mma.sync.aligned.m16n8k16.row.col.f32.bf16.bf16.f32 "
        "{%0,%1,%2,%3}, {%4,%5,%6,%7}, {%8,%9}, {%0,%1,%2,%3};"
        : "+f"(c[0]), "+f"(c[1]), "+f"(c[2]), "+f"(c[3])
        : "r"(a[0]), "r"(a[1]), "r"(a[2]), "r"(a[3]), "r"(b[0]), "r"(b[1]));
}
__device__ __forceinline__ float sigmoidf(float x) { return 1.0f / (1.0f + expf(-x)); }
__device__ __forceinline__ int packed_row(int q) { return (q & 3) * 1024 + (q >> 2); }

__device__ __forceinline__ void lstm_cell(float4 g, int t, float dd, int q, float c0,
                                          float& hn, float& cn) {
    float4 pv = *(const float4*)&g_P[t * GG + q];
    float4 wl = *(const float4*)&g_wlast[q];
    float4 bp = *(const float4*)&g_biasp[q];
    float gi = g.x + pv.x + dd * wl.x + bp.x;
    float gf = g.y + pv.y + dd * wl.y + bp.y;
    float gg = g.z + pv.z + dd * wl.z + bp.z;
    float go = g.w + pv.w + dd * wl.w + bp.w;
    cn = sigmoidf(gf) * c0 + sigmoidf(gi) * tanhf(gg);
    hn = sigmoidf(go) * tanhf(cn);
}

// ---------------- prep kernels ----------------
__global__ void prep_small_kernel(const float* __restrict__ W_ih,
                                  const float* __restrict__ b_ih,
                                  const float* __restrict__ b_hh) {
    int q = blockIdx.x * blockDim.x + threadIdx.x;
    if (q >= GG) return;
    int r = packed_row(q);
    g_biasp[q] = b_ih[r] + b_hh[r];
    g_wlast[q] = W_ih[(size_t)r * EE + (EE - 1)];
}

__global__ void conv_whh_kernel(const float* __restrict__ W_hh) {
    int q = blockIdx.x;
    int r = packed_row(q);
    for (int k = threadIdx.x; k < 1024; k += 256)
        g_Whi[(size_t)q * 1024 + k] = __float2bfloat16(W_hh[(size_t)r * 1024 + k]);
}

__global__ void compP_kernel(const float* __restrict__ emb_table,
                             const float* __restrict__ W_ih) {
    __shared__ float se[EE];
    int t = blockIdx.x;
    for (int i = threadIdx.x; i < EE; i += blockDim.x)
        se[i] = emb_table[(size_t)t * EE + i];
    __syncthreads();
    int q = blockIdx.y * blockDim.x + threadIdx.x;
    int r = packed_row(q);
    const float4* w = (const float4*)(W_ih + (size_t)r * EE);
    const float4* s4 = (const float4*)se;
    float acc = 0.f;
#pragma unroll 8
    for (int e = 0; e < EE / 4; e++) {
        float4 a = s4[e], b = w[e];
        acc += a.x * b.x + a.y * b.y + a.z * b.z + a.w * b.w;
    }
    g_P[t * GG + q] = acc;
}

__global__ void node_meta_kernel(const int* __restrict__ node_types,
                                 const float* __restrict__ node_args,
                                 const float* __restrict__ emb_table) {
    int i = blockIdx.x * blockDim.x + threadIdx.x;
    if (i >= PROC * BATCH) return;
    int node = i >> 6;
    int b = i & 63;
    int t = node_types[(size_t)b * NN + node];
    g_tnode[i] = t;
    float d = 0.f;
    if (t <= 1)
        d = node_args[(size_t)b * NN + node] - emb_table[(size_t)t * EE + (EE - 1)];
    g_dnode[i] = d;
}

// ---------------- leaf level (d=8): zero children ----------------
__global__ void leaf_level_kernel() {
    int node = 255 + blockIdx.x;
    int b = threadIdx.x;
    int h0 = blockIdx.y * 64;
    int ni = node * BATCH + b;
    int t = g_tnode[ni];
    float dd = g_dnode[ni];
    size_t base = ((size_t)node * BATCH + b) * HH;
    for (int g8 = 0; g8 < 8; g8++) {
        int hb = h0 + g8 * 8;
        __nv_bfloat16 hhi8[8];
        float c8[8];
#pragma unroll
        for (int j = 0; j < 8; j++) {
            int q = 4 * (hb + j);
            float4 pv = *(const float4*)&g_P[t * GG + q];
            float4 wl = *(const float4*)&g_wlast[q];
            float4 bp = *(const float4*)&g_biasp[q];
            float gi = pv.x + dd * wl.x + bp.x;
            float gg = pv.z + dd * wl.z + bp.z;
            float go = pv.w + dd * wl.w + bp.w;
            float cn = sigmoidf(gi) * tanhf(gg);
            float hn = sigmoidf(go) * tanhf(cn);
            c8[j] = cn;
            hhi8[j] = __float2bfloat16(hn);
        }
        *(uint4*)&g_hhi[base + hb] = *(uint4*)hhi8;
        *(float4*)&g_c[base + hb]     = *(float4*)c8;
        *(float4*)&g_c[base + hb + 4] = *(float4*)(c8 + 4);
    }
}

// ---------------- level GEMM: bf16 mma.sync, cp.async double-buffered ----------
__global__ void __launch_bounds__(256, 2) level_mma_kernel(int first, int count, int ksplit) {
    extern __shared__ char smem[];
    uint32_t sb = smem_u32(smem);
    float* Cs = (float*)smem;

    const int tid = threadIdx.x;
    const int lane = tid & 31;
    const int wid = tid >> 5;
    const int warp_m = wid & 3;
    const int warp_n = wid >> 2;

    const int p = blockIdx.x;
    const int n0 = first + 2 * p;
    const int n1 = (n0 + 1 <= first + count - 1) ? n0 + 1 : n0;
    const int q0 = blockIdx.y * BN;
    const int ks = blockIdx.z;
    const int chunks = 16 / ksplit;
    const int kc0 = ks * chunks;
    const int kcE = kc0 + chunks;

    int lrow[4], lcg[4];
#pragma unroll
    for (int it = 0; it < 4; it++) {
        int i = tid + it * 256;
        lrow[it] = i >> 3;
        lcg[it] = i & 7;
    }

    float acc[2][8][4];
#pragma unroll
    for (int mt = 0; mt < 2; mt++)
#pragma unroll
        for (int nt = 0; nt < 8; nt++)
#pragma unroll
            for (int i = 0; i < 4; i++) acc[mt][nt][i] = 0.f;

    auto issue = [&](int kc, int buf) {
        const int k0 = kc * BK;
        const int childbase = (k0 < 512) ? 1 : 2;
        const int kk = k0 & 511;
        const uint32_t base = sb + buf * ST_SZ;
#pragma unroll
        for (int it = 0; it < 4; it++) {
            int r = lrow[it], cg = lcg[it];
            int node = (r < 64) ? n0 : n1;
            int b = r & 63;
            size_t asrc = ((size_t)(2 * node + childbase) * BATCH + b) * HH + kk + cg * 8;
            size_t bsrc = (size_t)(q0 + r) * 1024 + k0 + cg * 8;
            uint32_t so = (uint32_t)(r * TSTRIDE + cg * 16);
            cp16(base + OFF_AHI + so, g_hhi + asrc);
            cp16(base + OFF_BHI + so, g_Whi + bsrc);
        }
    };

    issue(kc0, 0);
    CP_COMMIT();

    for (int kc = kc0; kc < kcE; kc++) {
        const int buf = (kc - kc0) & 1;
        if (kc + 1 < kcE) {
            issue(kc + 1, buf ^ 1);
            CP_COMMIT();
            cp_wait<1>();
        } else {
            cp_wait<0>();
        }
        __syncthreads();

        const uint32_t bufb = sb + buf * ST_SZ;
        const uint32_t a_off = (uint32_t)((warp_m * 32 + (lane & 15)) * TSTRIDE + (lane >> 4) * 16);
        const uint32_t b_off = (uint32_t)((warp_n * 64 + ((lane >> 4) << 3) + (lane & 7)) * TSTRIDE
                                          + (((lane >> 3) & 1) << 4));
#pragma unroll
        for (int kt = 0; kt < 4; kt++) {
            uint32_t ah[2][4];
            ldm_x4(ah[0], bufb + OFF_AHI + a_off + kt * 32);
            ldm_x4(ah[1], bufb + OFF_AHI + a_off + kt * 32 + 16 * TSTRIDE);
#pragma unroll
            for (int ng = 0; ng < 4; ng++) {
                uint32_t bh[4];
                ldm_x4(bh, bufb + OFF_BHI + b_off + kt * 32 + ng * 16 * TSTRIDE);
#pragma unroll
                for (int half = 0; half < 2; half++) {
                    int nt = ng * 2 + half;
#pragma unroll
                    for (int mt = 0; mt < 2; mt++)
                        mma_bf16(acc[mt][nt], ah[mt], bh + 2 * half);
                }
            }
        }
        __syncthreads();
    }

    // ---- stage C to smem (128 x 132 f32) ----
#pragma unroll
    for (int mt = 0; mt < 2; mt++)
#pragma unroll
        for (int nt = 0; nt < 8; nt++) {
            int r = warp_m * 32 + mt * 16 + (lane >> 2);
            int c = warp_n * 64 + nt * 8 + (lane & 3) * 2;
            *(float2*)&Cs[r * 132 + c]       = make_float2(acc[mt][nt][0], acc[mt][nt][1]);
            *(float2*)&Cs[(r + 8) * 132 + c] = make_float2(acc[mt][nt][2], acc[mt][nt][3]);
        }
    __syncthreads();

    if (ksplit == 1) {
        for (int idx = tid; idx < 128 * 32; idx += 256) {
            int r = idx >> 5, hg = idx & 31;
            if (r >= 64 && n1 == n0) continue;
            int node = (r < 64) ? n0 : n1;
            int b = r & 63;
            int ni = node * BATCH + b;
            int t = g_tnode[ni];
            float dd = g_dnode[ni];
            int hidx = (q0 >> 2) + hg;
            int q = q0 + hg * 4;
            float c0 = g_c[((size_t)(2 * node + 1) * BATCH + b) * HH + hidx];
            float4 g = *(const float4*)&Cs[r * 132 + hg * 4];
            float hn, cn;
            lstm_cell(g, t, dd, q, c0, hn, cn);
            size_t o = ((size_t)node * BATCH + b) * HH + hidx;
            g_hhi[o] = __float2bfloat16(hn);
            g_c[o] = cn;
            if (node == 0) g_hroot[b * HH + hidx] = hn;
        }
    } else {
        for (int i = tid; i < 128 * 32; i += 256) {
            int r = i >> 5, c4 = i & 31;
            int nl = 2 * p + (r >= 64 ? 1 : 0);
            if (nl >= count) continue;
            int b = r & 63;
            size_t dst = (((size_t)(ks * count + nl) * 64 + b) * 2048) + q0 + c4 * 4;
            *(float4*)&g_part[dst] = *(const float4*)&Cs[r * 132 + c4 * 4];
        }
    }
}

// ---------------- split-K reduction + LSTM ----------------
__global__ void level_reduce_kernel(int first, int count, int ksplit) {
    int nl = blockIdx.x;
    int node = first + nl;
    int q0 = blockIdx.y * BN;
    int tid = threadIdx.x;
    for (int idx = tid; idx < 64 * 32; idx += 256) {
        int b = idx >> 5, hg = idx & 31;
        int q = q0 + hg * 4;
        int hidx = (q0 >> 2) + hg;
        float4 s = make_float4(0.f, 0.f, 0.f, 0.f);
        for (int ks = 0; ks < ksplit; ks++) {
            const float4 v = *(const float4*)&g_part[(((size_t)(ks * count + nl) * 64 + b) * 2048) + q];
            s.x += v.x; s.y += v.y; s.z += v.z; s.w += v.w;
        }
        int ni = node * BATCH + b;
        int t = g_tnode[ni];
        float dd = g_dnode[ni];
        float c0 = g_c[((size_t)(2 * node + 1) * BATCH + b) * HH + hidx];
        float hn, cn;
        lstm_cell(s, t, dd, q, c0, hn, cn);
        size_t o = ((size_t)node * BATCH + b) * HH + hidx;
        g_hhi[o] = __float2bfloat16(hn);
        g_c[o] = cn;
        if (node == 0) g_hroot[b * HH + hidx] = hn;
    }
}

// ---------------- output head ----------------
__global__ void head_kernel(const float* __restrict__ W1, const float* __restrict__ b1,
                            const float* __restrict__ W2, const float* __restrict__ b2,
                            const float* __restrict__ validity, float* __restrict__ out) {
    int b = blockIdx.x;
    __shared__ float sh[HH];
    __shared__ float sx[HH];
    __shared__ float slog[OPS];
    const float* rh = g_hroot + (size_t)b * HH;
    for (int i = threadIdx.x; i < HH; i += blockDim.x) sh[i] = rh[i];
    __syncthreads();
    for (int j = threadIdx.x; j < HH; j += blockDim.x) {
        float acc = b1[j];
        const float4* w = (const float4*)(W1 + (size_t)j * HH);
        const float4* s4 = (const float4*)sh;
#pragma unroll 8
        for (int e = 0; e < HH / 4; e++) {
            float4 a = s4[e], ww = w[e];
            acc += a.x * ww.x + a.y * ww.y + a.z * ww.z + a.w * ww.w;
        }
        sx[j] = fmaxf(acc, 0.f);
    }
    __syncthreads();
    int warp = threadIdx.x >> 5, lane = threadIdx.x & 31;
    for (int o = warp; o < OPS; o += 8) {
        float acc = 0.f;
        const float* w = W2 + (size_t)o * HH;
        for (int e = lane; e < HH; e += 32) acc += sx[e] * w[e];
#pragma unroll
        for (int off = 16; off; off >>= 1) acc += __shfl_xor_sync(0xffffffff, acc, off);
        if (lane == 0) slog[o] = acc + b2[o] + logf(validity[b * OPS + o]);
    }
    __syncthreads();
    if (threadIdx.x == 0) {
        float mx = -1e30f;
        float v[OPS];
        for (int o = 0; o < OPS; o++) { v[o] = slog[o] / 3.0f; if (v[o] > mx) mx = v[o]; }
        float s = 0.f;
        for (int o = 0; o < OPS; o++) { v[o] = expf(v[o] - mx); s += v[o]; }
        float inv = 1.0f / s;
        for (int o = 0; o < OPS; o++) out[b * OPS + o] = v[o] * inv;
    }
}

// ---------------- launch ----------------
extern "C" void kernel_launch(void* const* d_in, const int* in_sizes, int n_in,
                              void* d_out, int out_size) {
    const int*   node_types = (const int*)d_in[0];
    const float* node_args  = (const float*)d_in[1];
    const float* validity   = (const float*)d_in[2];
    const float* emb_table  = (const float*)d_in[3];
    const float* W_ih       = (const float*)d_in[4];
    const float* W_hh       = (const float*)d_in[5];
    const float* b_ih       = (const float*)d_in[6];
    const float* b_hh       = (const float*)d_in[7];
    const float* W1         = (const float*)d_in[8];
    const float* b1         = (const float*)d_in[9];
    const float* W2         = (const float*)d_in[10];
    const float* b2         = (const float*)d_in[11];
    float* out = (float*)d_out;

    static bool attr_set = false;
    if (!attr_set) {
        cudaFuncSetAttribute(level_mma_kernel,
                             cudaFuncAttributeMaxDynamicSharedMemorySize, SMEM_BYTES);
        attr_set = true;
    }

    prep_small_kernel<<<(GG + 255) / 256, 256>>>(W_ih, b_ih, b_hh);
    conv_whh_kernel<<<GG, 256>>>(W_hh);
    compP_kernel<<<dim3(VOCAB, GG / 256), 256>>>(emb_table, W_ih);
    node_meta_kernel<<<(PROC * BATCH + 255) / 256, 256>>>(node_types, node_args, emb_table);

    leaf_level_kernel<<<dim3(256, 8), 64>>>();

    for (int d = 7; d >= 0; --d) {
        int first = (1 << d) - 1;
        int count = 1 << d;
        int sk = (d >= 5) ? 1 : (d == 4 ? 2 : (d == 3 ? 4 : 8));
        dim3 grid((count + 1) / 2, GG / BN, sk);
        level_mma_kernel<<<grid, 256, SMEM_BYTES>>>(first, count, sk);
        if (sk > 1)
            level_reduce_kernel<<<dim3(count, GG / BN), 256>>>(first, count, sk);
    }

    head_kernel<<<BATCH, 256>>>(W1, b1, W2, b2, validity, out);
}